// round 3
// baseline (speedup 1.0000x reference)
#include <cuda_runtime.h>

// Problem constants
#define BQ 256
#define NQ 512
#define EQ 64
#define OQ 64
#define KQ 8

// Scratch (device globals: allocation-free rule)
__device__ float g_priors[BQ * NQ * OQ];        // 33.5 MB  [b][n][o]
__device__ float g_s[BQ * NQ * KQ];             // 4 MB     [b][n][k]  cumulative logit shift
__device__ float g_zpart[4 * BQ * KQ * OQ];     // 2 MB     [slot][b][k][o]
__device__ float g_v[BQ * KQ * OQ];             // 0.5 MB   [b][k][o]

// ---------------------------------------------------------------------------
// priors = emb @ S : (131072 x 64) @ (64 x 64), fp32
// Block computes a 64(row) x 64(col) tile, thread 4x4 micro-tile.
// ---------------------------------------------------------------------------
__global__ __launch_bounds__(256) void gemm_kernel(const float* __restrict__ A,
                                                   const float* __restrict__ S) {
    __shared__ float At[64 * 68];   // At[e*68 + r]  (A transposed for float4 frag loads)
    __shared__ float Bs[64 * 68];   // Bs[e*68 + o]

    int tid = threadIdx.x;
    size_t row0 = (size_t)blockIdx.x * 64;

    const float4* a4 = (const float4*)(A + row0 * 64);
    for (int i = tid; i < 1024; i += 256) {
        float4 v = a4[i];
        int r = i >> 4, c = (i & 15) << 2;
        At[(c + 0) * 68 + r] = v.x;
        At[(c + 1) * 68 + r] = v.y;
        At[(c + 2) * 68 + r] = v.z;
        At[(c + 3) * 68 + r] = v.w;
    }
    const float4* b4 = (const float4*)S;
    for (int i = tid; i < 1024; i += 256) {
        float4 v = b4[i];
        int e = i >> 4, c = (i & 15) << 2;
        float* row = &Bs[e * 68 + c];
        row[0] = v.x; row[1] = v.y; row[2] = v.z; row[3] = v.w;
    }
    __syncthreads();

    int ty = tid >> 4, tx = tid & 15;
    float acc[4][4] = {};
#pragma unroll 16
    for (int e = 0; e < 64; e++) {
        float af[4], bf[4];
        *(float4*)af = *(const float4*)&At[e * 68 + ty * 4];
        *(float4*)bf = *(const float4*)&Bs[e * 68 + tx * 4];
#pragma unroll
        for (int i = 0; i < 4; i++)
#pragma unroll
            for (int j = 0; j < 4; j++)
                acc[i][j] = fmaf(af[i], bf[j], acc[i][j]);
    }
#pragma unroll
    for (int i = 0; i < 4; i++) {
        float4 v = make_float4(acc[i][0], acc[i][1], acc[i][2], acc[i][3]);
        *(float4*)&g_priors[(row0 + ty * 4 + i) * 64 + tx * 4] = v;
    }
}

// ---------------------------------------------------------------------------
// Routing pass. One block = (b, 128-row n-slice). MODE:
//   0: s = 0 (first pass)
//   1: s = sim(v)             (write g_s)
//   2: s = g_s + sim(v)       (final pass, no write)
// Computes softmax over K per (n,o), accumulates z partial into g_zpart.
// ---------------------------------------------------------------------------
template <int MODE>
__global__ __launch_bounds__(256) void pass_kernel(const float* __restrict__ cc) {
    __shared__ float p_sm[128 * 65];   // priors tile [nl][o] padded; reused for z reduce
    __shared__ float s_sm[128 * 8];    // logit shifts [nl][k]
    __shared__ float v_sm[64 * 8];     // v transposed [o][k]

    int tid = threadIdx.x;
    int b = blockIdx.y;
    int n0 = blockIdx.x * 128;

    // ---- Phase A: stage priors tile (+v) in SMEM ----
    const float4* psrc = (const float4*)(g_priors + ((size_t)b * NQ + n0) * OQ);
    for (int i4 = tid; i4 < 2048; i4 += 256) {
        float4 v = psrc[i4];
        int nl = i4 >> 4, oc = (i4 & 15) << 2;
        float* d = &p_sm[nl * 65 + oc];
        d[0] = v.x; d[1] = v.y; d[2] = v.z; d[3] = v.w;
    }
    if (MODE != 0) {
        for (int i = tid; i < 512; i += 256) {
            float vv = g_v[(size_t)b * 512 + i];
            int k = i >> 6, o2 = i & 63;
            v_sm[o2 * 8 + k] = vv;
        }
    }
    __syncthreads();

    // ---- Phase B: per-n logit shifts s[k,n] (fused sim dot-products) ----
    if (MODE == 0) {
        for (int i = tid; i < 1024; i += 256) s_sm[i] = 0.f;
    } else {
        int nl = tid >> 1;
        int kq = (tid & 1) << 2;
        const float* prow = &p_sm[nl * 65];
        float a0 = 0.f, a1 = 0.f, a2 = 0.f, a3 = 0.f;
#pragma unroll
        for (int o2 = 0; o2 < 64; o2++) {
            float p = prow[o2];
            float4 vv = *(const float4*)&v_sm[o2 * 8 + kq];
            a0 = fmaf(p, vv.x, a0);
            a1 = fmaf(p, vv.y, a1);
            a2 = fmaf(p, vv.z, a2);
            a3 = fmaf(p, vv.w, a3);
        }
        size_t sidx = ((size_t)b * NQ + n0 + nl) * 8 + kq;
        if (MODE == 2) {
            float4 sp = *(const float4*)&g_s[sidx];
            a0 += sp.x; a1 += sp.y; a2 += sp.z; a3 += sp.w;
        }
        float4 res = make_float4(a0, a1, a2, a3);
        *(float4*)&s_sm[nl * 8 + kq] = res;
        if (MODE == 1) *(float4*)&g_s[sidx] = res;
    }
    __syncthreads();

    // ---- Phase C: stream cc, softmax over K, accumulate z ----
    int o = tid & 63;
    int lane = tid >> 6;                       // 0..3
    const float* ccb = cc + (size_t)b * (KQ * NQ * OQ);
    float acc[8] = {0.f, 0.f, 0.f, 0.f, 0.f, 0.f, 0.f, 0.f};

#pragma unroll 2
    for (int i = 0; i < 32; i++) {
        int nl = lane + (i << 2);
        int n = n0 + nl;
        float t[8];
#pragma unroll
        for (int k = 0; k < 8; k++)
            t[k] = __ldg(&ccb[((size_t)((k << 9) + n)) * 64 + o]);
        float4 sa = *(const float4*)&s_sm[nl * 8];
        float4 sb = *(const float4*)&s_sm[nl * 8 + 4];
        t[0] += sa.x; t[1] += sa.y; t[2] += sa.z; t[3] += sa.w;
        t[4] += sb.x; t[5] += sb.y; t[6] += sb.z; t[7] += sb.w;
        float m = t[0];
#pragma unroll
        for (int k = 1; k < 8; k++) m = fmaxf(m, t[k]);
        float e[8], dsum = 0.f;
#pragma unroll
        for (int k = 0; k < 8; k++) { e[k] = __expf(t[k] - m); dsum += e[k]; }
        float pr = p_sm[nl * 65 + o] * __fdividef(1.f, dsum);
#pragma unroll
        for (int k = 0; k < 8; k++) acc[k] = fmaf(e[k], pr, acc[k]);
    }

    // ---- z reduce across the 4 n-lanes (reuse p_sm) ----
    __syncthreads();
#pragma unroll
    for (int k = 0; k < 8; k++)
        p_sm[(lane * 8 + k) * 64 + o] = acc[k];
    __syncthreads();
    for (int j = tid; j < 512; j += 256) {
        float z = p_sm[j] + p_sm[512 + j] + p_sm[1024 + j] + p_sm[1536 + j];
        g_zpart[((size_t)blockIdx.x * BQ + b) * (KQ * OQ) + j] = z;
    }
}

// ---------------------------------------------------------------------------
// squash: sum the 4 z partials, v = (||z||^2/(1+||z||^2)) * z / sqrt(||z||^2+eps)
// One warp per (b,k) vector of length 64.
// ---------------------------------------------------------------------------
template <bool FINAL>
__global__ __launch_bounds__(256) void squash_kernel(float* __restrict__ out) {
    int w = (blockIdx.x * 256 + threadIdx.x) >> 5;    // 0..2047 = b*8+k
    int lane = threadIdx.x & 31;
    const int SL = BQ * KQ * OQ;                      // 131072
    int base = w * 64;

    float z0 = g_zpart[base + lane] + g_zpart[SL + base + lane] +
               g_zpart[2 * SL + base + lane] + g_zpart[3 * SL + base + lane];
    int l2 = lane + 32;
    float z1 = g_zpart[base + l2] + g_zpart[SL + base + l2] +
               g_zpart[2 * SL + base + l2] + g_zpart[3 * SL + base + l2];

    float sq = z0 * z0 + z1 * z1;
#pragma unroll
    for (int off = 16; off; off >>= 1) sq += __shfl_xor_sync(0xffffffffu, sq, off);

    float denom = (1.0f + sq) * __fsqrt_rn(sq + 1e-9f);
    float f = __fdiv_rn(sq, denom);

    float* dst = FINAL ? out : g_v;
    dst[base + lane] = z0 * f;
    dst[base + l2]  = z1 * f;
}

// ---------------------------------------------------------------------------
extern "C" void kernel_launch(void* const* d_in, const int* in_sizes, int n_in,
                              void* d_out, int out_size) {
    // Expected order per setup_inputs: emb_inputs, S, coup_coeff.
    const float* emb = (const float*)d_in[0];
    const float* S   = (const float*)d_in[1];
    const float* cc  = (const float*)d_in[2];
    // Size-based matching as a safety net (all sizes are distinct).
    for (int i = 0; i < n_in; i++) {
        if (in_sizes[i] == BQ * NQ * EQ)            emb = (const float*)d_in[i];
        else if (in_sizes[i] == EQ * OQ)            S = (const float*)d_in[i];
        else if (in_sizes[i] == BQ * KQ * NQ * OQ)  cc = (const float*)d_in[i];
    }
    float* out = (float*)d_out;

    gemm_kernel<<<2048, 256>>>(emb, S);

    dim3 pg(4, BQ);
    pass_kernel<0><<<pg, 256>>>(cc);
    squash_kernel<false><<<256, 256>>>(nullptr);

    pass_kernel<1><<<pg, 256>>>(cc);
    squash_kernel<false><<<256, 256>>>(nullptr);

    pass_kernel<2><<<pg, 256>>>(cc);
    squash_kernel<true><<<256, 256>>>(out);
}